// round 1
// baseline (speedup 1.0000x reference)
#include <cuda_runtime.h>

// InstHead fused kernel, fp32, f32x2-packed FMA, two passes over feats.
// Pass1: h-stats (for BN) + mask MLP + segment sums (pooled).
// Finalize: BN fold into W1', pooled means, iou scores.
// Pass2: folded offset MLP -> pt_offsets.

#define C 32
#define WPB 4           // warps per block
typedef unsigned long long u64;

__device__ __forceinline__ u64 fma2(u64 a, u64 b, u64 c) {
    u64 d;
    asm("fma.rn.f32x2 %0, %1, %2, %3;" : "=l"(d) : "l"(a), "l"(b), "l"(c));
    return d;
}
__device__ __forceinline__ u64 pack2(float lo, float hi) {
    u64 d;
    asm("mov.b64 %0, {%1, %2};" : "=l"(d) : "f"(lo), "f"(hi));
    return d;
}
__device__ __forceinline__ float sum2(u64 a) {
    float l, h;
    asm("mov.b64 {%0, %1}, %2;" : "=f"(l), "=f"(h) : "l"(a));
    return l + h;
}

// ---- scratch (device globals; no allocation allowed) ----
__device__ float g_pool[64 * C];
__device__ float g_cnt[64];
__device__ float g_sumH[C];
__device__ float g_sumH2[C];
__device__ float g_w1f[C * C];
__device__ float g_b1f[C];

__global__ void zero_kernel(int B) {
    int t = threadIdx.x;
    for (int i = t; i < B * C; i += blockDim.x) g_pool[i] = 0.f;
    if (t < B) g_cnt[t] = 0.f;
    if (t < C) { g_sumH[t] = 0.f; g_sumH2[t] = 0.f; }
}

// ================= PASS 1 =================
__global__ void __launch_bounds__(32 * WPB) pass1_kernel(
    const float* __restrict__ feats, const int* __restrict__ bidx,
    const float* __restrict__ w1,  const float* __restrict__ b1,
    const float* __restrict__ mw1, const float* __restrict__ mb1,
    const float* __restrict__ mw2, const float* __restrict__ mb2,
    float* __restrict__ mask_out, int n, int tiles_total, int tpw)
{
    __shared__ float sx[WPB][32 * 36];   // staged feats tile, [point][k], pitch 36
    __shared__ float sm[WPB][32 * 33];   // relu'd mask hidden, [point][t], pitch 33
    __shared__ int   sb[WPB][32];
    __shared__ float s_mw2[C];
    __shared__ float s_mb2;

    const int lane = threadIdx.x & 31;
    const int wi   = threadIdx.x >> 5;
    if (threadIdx.x < C) s_mw2[threadIdx.x] = mw2[threadIdx.x];
    if (threadIdx.x == 0) s_mb2 = mb2[0];
    __syncthreads();

    // lane = output channel; weights in registers, packed over k-pairs
    u64 w1p[16], mw1p[16];
#pragma unroll
    for (int kk = 0; kk < 16; kk++) {
        w1p[kk]  = pack2(w1[(2 * kk) * C + lane],  w1[(2 * kk + 1) * C + lane]);
        mw1p[kk] = pack2(mw1[(2 * kk) * C + lane], mw1[(2 * kk + 1) * C + lane]);
    }
    const float b1t  = b1[lane];
    const float mb1t = mb1[lane];

    float sumH = 0.f, sumH2 = 0.f;
    float pacc = 0.f;
    int   pcnt = 0;
    int   cur_b = -1;

    const int gwid = blockIdx.x * WPB + wi;
    int t0 = gwid * tpw;
    int t1 = t0 + tpw; if (t1 > tiles_total) t1 = tiles_total;

    float* SX = sx[wi];
    float* SM = sm[wi];
    int*   SB = sb[wi];

    for (int tile = t0; tile < t1; tile++) {
        const int base  = tile * 32;
        int valid = n - base; if (valid > 32) valid = 32;
        const int lim = valid * 8;
        const float4* src = (const float4*)(feats + (size_t)base * C);
#pragma unroll
        for (int j = 0; j < 8; j++) {
            int L = lane + 32 * j;
            float4 v = make_float4(0.f, 0.f, 0.f, 0.f);
            if (L < lim) v = src[L];
            *(float4*)&SX[(L >> 3) * 36 + 4 * (L & 7)] = v;
        }
        if (lane < valid) SB[lane] = bidx[base + lane];
        __syncwarp();

        for (int p = 0; p < valid; p++) {
            const float* xp = &SX[p * 36];
            u64 h2a = pack2(b1t, 0.f),  h2b = pack2(0.f, 0.f);
            u64 m2a = pack2(mb1t, 0.f), m2b = pack2(0.f, 0.f);
#pragma unroll
            for (int kk = 0; kk < 16; kk += 2) {
                u64 xa = *(const u64*)&xp[2 * kk];
                u64 xb = *(const u64*)&xp[2 * kk + 2];
                h2a = fma2(xa, w1p[kk],      h2a);
                m2a = fma2(xa, mw1p[kk],     m2a);
                h2b = fma2(xb, w1p[kk + 1],  h2b);
                m2b = fma2(xb, mw1p[kk + 1], m2b);
            }
            float h = sum2(h2a) + sum2(h2b);
            sumH += h;
            sumH2 = fmaf(h, h, sumH2);
            float m = fmaxf(sum2(m2a) + sum2(m2b), 0.f);
            SM[p * 33 + lane] = m;

            int b = SB[p];
            if (b != cur_b) {
                if (cur_b >= 0) {
                    atomicAdd(&g_pool[cur_b * C + lane], pacc);
                    if (lane == 0) atomicAdd(&g_cnt[cur_b], (float)pcnt);
                }
                cur_b = b; pacc = 0.f; pcnt = 0;
            }
            pacc += xp[lane];
            pcnt++;
        }
        __syncwarp();
        if (lane < valid) {
            const float* mr = &SM[lane * 33];
            float a0 = s_mb2, a1 = 0.f;
#pragma unroll
            for (int k = 0; k < 32; k += 2) {
                a0 = fmaf(mr[k],     s_mw2[k],     a0);
                a1 = fmaf(mr[k + 1], s_mw2[k + 1], a1);
            }
            mask_out[base + lane] = a0 + a1;
        }
        __syncwarp();
    }

    if (cur_b >= 0) {
        atomicAdd(&g_pool[cur_b * C + lane], pacc);
        if (lane == 0) atomicAdd(&g_cnt[cur_b], (float)pcnt);
    }
    atomicAdd(&g_sumH[lane], sumH);
    atomicAdd(&g_sumH2[lane], sumH2);
}

// ================= FINALIZE =================
__global__ void finalize_kernel(
    const float* __restrict__ w1, const float* __restrict__ b1,
    const float* __restrict__ gamma, const float* __restrict__ beta,
    const float* __restrict__ iou_w, const float* __restrict__ iou_b,
    float* __restrict__ out_pooled, float* __restrict__ out_iou,
    int n, int B)
{
    int t = threadIdx.x;  // 0..31, channel
    float inv = 1.f / (float)n;
    float mu  = g_sumH[t] * inv;
    float var = g_sumH2[t] * inv - mu * mu;
    float s   = gamma[t] * rsqrtf(var + 1e-4f);
    g_b1f[t] = beta[t] + (b1[t] - mu) * s;
#pragma unroll
    for (int k = 0; k < C; k++) g_w1f[k * C + t] = w1[k * C + t] * s;

    float iw = iou_w[t];
    for (int b = 0; b < B; b++) {
        float cnt = fmaxf(g_cnt[b], 1.f);
        float pm  = g_pool[b * C + t] / cnt;
        out_pooled[b * C + t] = pm;
        float v = pm * iw;
#pragma unroll
        for (int o = 16; o > 0; o >>= 1) v += __shfl_xor_sync(0xffffffffu, v, o);
        if (t == 0) out_iou[b] = v + iou_b[0];
    }
}

// ================= PASS 2 =================
__global__ void __launch_bounds__(32 * WPB) pass2_kernel(
    const float* __restrict__ feats,
    const float* __restrict__ w2, const float* __restrict__ ob2,
    float* __restrict__ off_out, int n, int tiles_total, int tpw)
{
    __shared__ float sx[WPB][32 * 36];
    __shared__ float sy[WPB][32 * 34];  // pitch 34 (even) so LDS.64 stays aligned

    const int lane = threadIdx.x & 31;
    const int wi   = threadIdx.x >> 5;

    u64 w1p[16];
#pragma unroll
    for (int kk = 0; kk < 16; kk++)
        w1p[kk] = pack2(g_w1f[(2 * kk) * C + lane], g_w1f[(2 * kk + 1) * C + lane]);
    const float b1t = g_b1f[lane];

    u64 w2p0[16], w2p1[16], w2p2[16];
#pragma unroll
    for (int kk = 0; kk < 16; kk++) {
        w2p0[kk] = pack2(w2[(2 * kk) * 3 + 0], w2[(2 * kk + 1) * 3 + 0]);
        w2p1[kk] = pack2(w2[(2 * kk) * 3 + 1], w2[(2 * kk + 1) * 3 + 1]);
        w2p2[kk] = pack2(w2[(2 * kk) * 3 + 2], w2[(2 * kk + 1) * 3 + 2]);
    }
    const float c0 = ob2[0], c1 = ob2[1], c2 = ob2[2];

    const int gwid = blockIdx.x * WPB + wi;
    int t0 = gwid * tpw;
    int t1 = t0 + tpw; if (t1 > tiles_total) t1 = tiles_total;

    float* SX = sx[wi];
    float* SY = sy[wi];

    for (int tile = t0; tile < t1; tile++) {
        const int base = tile * 32;
        int valid = n - base; if (valid > 32) valid = 32;
        const int lim = valid * 8;
        const float4* src = (const float4*)(feats + (size_t)base * C);
#pragma unroll
        for (int j = 0; j < 8; j++) {
            int L = lane + 32 * j;
            float4 v = make_float4(0.f, 0.f, 0.f, 0.f);
            if (L < lim) v = src[L];
            *(float4*)&SX[(L >> 3) * 36 + 4 * (L & 7)] = v;
        }
        __syncwarp();

        for (int p = 0; p < valid; p++) {
            const float* xp = &SX[p * 36];
            u64 h2a = pack2(b1t, 0.f), h2b = pack2(0.f, 0.f);
#pragma unroll
            for (int kk = 0; kk < 16; kk += 2) {
                u64 xa = *(const u64*)&xp[2 * kk];
                u64 xb = *(const u64*)&xp[2 * kk + 2];
                h2a = fma2(xa, w1p[kk],     h2a);
                h2b = fma2(xb, w1p[kk + 1], h2b);
            }
            SY[p * 34 + lane] = fmaxf(sum2(h2a) + sum2(h2b), 0.f);
        }
        __syncwarp();

        if (lane < valid) {
            const float* yr = &SY[lane * 34];
            u64 a0 = pack2(c0, 0.f), a1 = pack2(c1, 0.f), a2 = pack2(c2, 0.f);
#pragma unroll
            for (int kk = 0; kk < 16; kk++) {
                u64 y2 = *(const u64*)&yr[2 * kk];
                a0 = fma2(y2, w2p0[kk], a0);
                a1 = fma2(y2, w2p1[kk], a1);
                a2 = fma2(y2, w2p2[kk], a2);
            }
            size_t o = (size_t)(base + lane) * 3;
            off_out[o + 0] = sum2(a0);
            off_out[o + 1] = sum2(a1);
            off_out[o + 2] = sum2(a2);
        }
        __syncwarp();
    }
}

// ================= LAUNCH =================
extern "C" void kernel_launch(void* const* d_in, const int* in_sizes, int n_in,
                              void* d_out, int out_size) {
    const float* feats = (const float*)d_in[0];
    const int*   bidx  = (const int*)  d_in[1];
    const float* w1    = (const float*)d_in[2];
    const float* b1    = (const float*)d_in[3];
    const float* gamma = (const float*)d_in[4];
    const float* beta  = (const float*)d_in[5];
    const float* w2    = (const float*)d_in[6];
    const float* ob2   = (const float*)d_in[7];
    const float* mw1   = (const float*)d_in[8];
    const float* mb1   = (const float*)d_in[9];
    const float* mw2   = (const float*)d_in[10];
    const float* mb2   = (const float*)d_in[11];
    const float* iw    = (const float*)d_in[12];
    const float* ib    = (const float*)d_in[13];

    int n = in_sizes[1];                       // N points
    int B = (out_size - 4 * n) / 33;           // pooled B*32 + iou B
    if (B < 1) B = 1;
    if (B > 64) B = 64;

    float* out        = (float*)d_out;
    float* out_off    = out;                       // [N,3]
    float* out_mask   = out + (size_t)3 * n;       // [N]
    float* out_pooled = out + (size_t)4 * n;       // [B,32]
    float* out_iou    = out_pooled + (size_t)B * C;// [B]

    int tiles  = (n + 31) / 32;
    int blocks = 608;                          // 152 SMs * 4
    int warps  = blocks * WPB;
    int tpw    = (tiles + warps - 1) / warps;

    zero_kernel<<<1, 1024>>>(B);
    pass1_kernel<<<blocks, 32 * WPB>>>(feats, bidx, w1, b1, mw1, mb1, mw2, mb2,
                                       out_mask, n, tiles, tpw);
    finalize_kernel<<<1, 32>>>(w1, b1, gamma, beta, iw, ib,
                               out_pooled, out_iou, n, B);
    pass2_kernel<<<blocks, 32 * WPB>>>(feats, w2, ob2, out_off, n, tiles, tpw);
}